// round 4
// baseline (speedup 1.0000x reference)
#include <cuda_runtime.h>
#include <cstdint>
#include <float.h>
#include <math.h>

#define NB 16384
#define NJ 16384
#define NKF 64
#define NDIM 128
#define N_ELEM (NB * NDIM)
#define N_STAT_BLOCKS 2048
#define JSPLIT 16
#define JCHUNK (NJ / JSPLIT)

typedef unsigned long long ull;

// Scratch (device globals; no allocation allowed)
__device__ float g_zf2T[NKF * NB];     // 2*zf folded, [kf][b]
__device__ float g_zf2R[NB * NKF];     // 2*zf folded, row-major [b][kf]
__device__ float g_znorm[NB];
__device__ float g_ef2T[NKF * NJ];     // folded e sums, [kf][j]
__device__ ull   g_k1[NB * JSPLIT];    // per (row, split) best key (score|j)
__device__ ull   g_k2[NB * JSPLIT];    // second best key
__device__ unsigned g_v3[NB * JSPLIT]; // third-smallest score (sortable u32)
__device__ int   g_idx[NB];
__device__ int   g_fbn;
__device__ int   g_fb[NB];
__device__ float g_partials[N_STAT_BLOCKS * 6];
__device__ float g_colpart[128 * 128];
__device__ float g_colmax;

// ---------------------------------------------------------------------------
__device__ __forceinline__ uint32_t smem_u32(const void* p) {
    uint32_t r;
    asm("{ .reg .u64 t; cvta.to.shared.u64 t, %1; cvt.u32.u64 %0, t; }"
        : "=r"(r) : "l"(p));
    return r;
}
__device__ __forceinline__ void lds_v2u64(ull& x, ull& y, uint32_t addr) {
    asm volatile("ld.shared.v2.u64 {%0,%1}, [%2];" : "=l"(x), "=l"(y) : "r"(addr));
}
__device__ __forceinline__ void ffma2(ull& d, ull a, ull b) {
    asm("fma.rn.f32x2 %0, %1, %2, %0;" : "+l"(d) : "l"(a), "l"(b));
}
__device__ __forceinline__ void unpack2(float& lo, float& hi, ull v) {
    asm("mov.b64 {%0,%1}, %2;" : "=f"(lo), "=f"(hi) : "l"(v));
}
__device__ __forceinline__ ull dup32(unsigned x) {
    ull a;
    asm("mov.b64 %0, {%1,%1};" : "=l"(a) : "r"(x));
    return a;
}
__device__ __forceinline__ void cp_async16(uint32_t dst, const void* src) {
    asm volatile("cp.async.cg.shared.global [%0], [%1], 16;"
                 :: "r"(dst), "l"(src));
}
__device__ __forceinline__ void cp_commit() {
    asm volatile("cp.async.commit_group;");
}
__device__ __forceinline__ void cp_wait0() {
    asm volatile("cp.async.wait_group 0;");
}

// Exact-chain fold map: kf(k) = (k>>6)*32 + (((k>>3)&7)<<2) + (k&3)
__device__ __forceinline__ int kf_of_k(int k) {
    return ((k >> 6) << 5) + (((k >> 3) & 7) << 2) + (k & 3);
}

// streaming top-3 insert (keys sortable u64 = score_bits<<32 | j)
__device__ __forceinline__ void top3_insert(ull K, ull& k1, ull& k2, unsigned& v3) {
    if (K < k1) { v3 = (unsigned)(k2 >> 32); k2 = k1; k1 = K; }
    else if (K < k2) { v3 = (unsigned)(k2 >> 32); k2 = K; }
    else { unsigned s = (unsigned)(K >> 32); if (s < v3) v3 = s; }
}

// ---------------------------------------------------------------------------
// zf2T[kf][b], zf2R[b][kf] = fl(z[b,c,h,2w'] + z[b,c,h,2w'+1]);
// znorm[b] = 0.5*sum(zf2^2). Also resets fallback counter.
// ---------------------------------------------------------------------------
__global__ void prep_z_kernel(const float* __restrict__ z) {
    int b = blockIdx.x * 128 + threadIdx.x;
    if (b == 0) g_fbn = 0;
    const float* zr = z + (size_t)b * NDIM;
    float sum = 0.f;
#pragma unroll
    for (int kf = 0; kf < NKF; kf++) {
        int c = kf >> 2, h = (kf >> 1) & 1, wp = kf & 1;
        int base = c * 8 + h * 4 + wp * 2;
        float2 p = *reinterpret_cast<const float2*>(zr + base);
        float v = p.x + p.y;
        g_zf2T[kf * NB + b] = v;
        g_zf2R[b * NKF + kf] = v;
        sum = fmaf(v, v, sum);
    }
    g_znorm[b] = 0.5f * sum;
}

// ---------------------------------------------------------------------------
// ef2T[kf][j] = fl(e[j][ka] + e[j][kb]) with (ka,kb) = inverse of kf_of_k.
// kf = ks*32 + g*4 + r  ->  ka = ks*64 + g*8 + r, kb = ka + 4.
// ---------------------------------------------------------------------------
__global__ void fold_e_kernel(const float* __restrict__ e) {
    int j = blockIdx.x * 128 + threadIdx.x;
    const float* er = e + (size_t)j * NDIM;
#pragma unroll
    for (int kf = 0; kf < NKF; kf++) {
        int ks = kf >> 5, q = kf & 31, g = q >> 2, r = q & 3;
        int ka = ks * 64 + g * 8 + r;
        g_ef2T[kf * NJ + j] = er[ka] + er[ka + 4];
    }
}

// ---------------------------------------------------------------------------
__global__ void colmax1_kernel(const float* __restrict__ e) {
    int t = threadIdx.x;
    int r0 = blockIdx.x * 128;
    float s = 0.f;
    for (int r = 0; r < 128; r++)
        s += fabsf(e[(size_t)(r0 + r) * NDIM + t]);
    g_colpart[blockIdx.x * 128 + t] = s;
}
__global__ void colmax2_kernel() {
    __shared__ float sm[128];
    int t = threadIdx.x;
    float s = 0.f;
    for (int bi = 0; bi < 128; bi++) s += g_colpart[bi * 128 + t];
    sm[t] = s;
    __syncthreads();
    for (int off = 64; off > 0; off >>= 1) {
        if (t < off) sm[t] = fmaxf(sm[t], sm[t + off]);
        __syncthreads();
    }
    if (t == 0) g_colmax = sm[0];
}

// ---------------------------------------------------------------------------
// Pass 1: folded K=64 FFMA2 GEMM; per (row, jsplit-block) emit best-2 keys
// + exact 3rd-smallest score. cp.async double-buffered e chunks.
// Block: 64 rows x 1024 codes, 128 threads, 8 rows x 8 cols/thread.
// ---------------------------------------------------------------------------
__global__ void __launch_bounds__(128, 3) pass1_kernel() {
    __shared__ float zf_s[NKF][64];       // 16 KB
    __shared__ float e_s[2][32][128];     // 32 KB double buffer

    int tid = threadIdx.x;
    int tm8 = (tid >> 4) * 8;
    int tn8 = (tid & 15) * 8;
    int row0 = (blockIdx.x & 255) * 64;
    int jsplit = blockIdx.x >> 8;
    int jbase = jsplit * JCHUNK;

    // stage zf tile [64 kf][64 rows]
#pragma unroll
    for (int it = 0; it < 8; it++) {
        int f4 = it * 128 + tid;
        int kf = f4 >> 4, m4 = f4 & 15;
        *reinterpret_cast<float4*>(&zf_s[kf][m4 * 4]) =
            *reinterpret_cast<const float4*>(&g_zf2T[kf * NB + row0 + m4 * 4]);
    }
    float zn[8];
#pragma unroll
    for (int r = 0; r < 8; r++) zn[r] = g_znorm[row0 + tm8 + r];

    ull k1[8], k2[8];
    unsigned v3[8];
#pragma unroll
    for (int r = 0; r < 8; r++) { k1[r] = ~0ULL; k2[r] = ~0ULL; v3[r] = 0xFFFFFFFFu; }

    uint32_t sb0 = smem_u32(&e_s[0][0][0]) + tn8 * 4;
    uint32_t sb1 = smem_u32(&e_s[1][0][0]) + tn8 * 4;

    // chunk c = t*2 + ks : rows kf = ks*32.., cols j = jbase + t*128..
    // issue chunk c into buffer c&1
    int kkL = tid >> 5, n4L = tid & 31;           // per-thread ld pattern
    auto src_of = [&](int c) {
        int t = c >> 1, ks = c & 1;
        return g_ef2T + (size_t)(ks * 32) * NJ + jbase + t * 128;
    };
    {
        const float* src = src_of(0);
        uint32_t dst = smem_u32(&e_s[0][0][0]);
#pragma unroll
        for (int it = 0; it < 8; it++) {
            int kk = it * 4 + kkL;
            cp_async16(dst + kk * 512 + n4L * 16, src + (size_t)kk * NJ + n4L * 4);
        }
        cp_commit();
    }

    for (int t = 0; t < JCHUNK / 128; t++) {
        ull acc[8][4];
#pragma unroll
        for (int r = 0; r < 8; r++)
#pragma unroll
            for (int c = 0; c < 4; c++) acc[r][c] = 0ULL;

#pragma unroll
        for (int ks = 0; ks < 2; ks++) {
            int c = t * 2 + ks;
            cp_wait0();
            __syncthreads();
            if (c < JCHUNK / 64 - 1) {
                const float* src = src_of(c + 1);
                uint32_t dst = smem_u32(&e_s[(c + 1) & 1][0][0]);
#pragma unroll
                for (int it = 0; it < 8; it++) {
                    int kk = it * 4 + kkL;
                    cp_async16(dst + kk * 512 + n4L * 16,
                               src + (size_t)kk * NJ + n4L * 4);
                }
                cp_commit();
            }
            uint32_t sbb = (c & 1) ? sb1 : sb0;
#pragma unroll
            for (int kk = 0; kk < 32; kk++) {
                uint4 av0 = *reinterpret_cast<const uint4*>(&zf_s[ks * 32 + kk][tm8]);
                uint4 av1 = *reinterpret_cast<const uint4*>(&zf_s[ks * 32 + kk][tm8 + 4]);
                ull b0, b1, b2, b3;
                lds_v2u64(b0, b1, sbb + kk * 512);
                lds_v2u64(b2, b3, sbb + kk * 512 + 16);
                ull a[8];
                a[0] = dup32(av0.x); a[1] = dup32(av0.y);
                a[2] = dup32(av0.z); a[3] = dup32(av0.w);
                a[4] = dup32(av1.x); a[5] = dup32(av1.y);
                a[6] = dup32(av1.z); a[7] = dup32(av1.w);
                ull bv[4] = {b0, b1, b2, b3};
#pragma unroll
                for (int r = 0; r < 8; r++)
#pragma unroll
                    for (int cc = 0; cc < 4; cc++)
                        ffma2(acc[r][cc], a[r], bv[cc]);
            }
        }

        // epilogue: s = fl(zn - dot) > 0; sortable u32 = raw bits.
        int jt = jbase + t * 128 + tn8;
#pragma unroll
        for (int cp = 0; cp < 4; cp++) {
#pragma unroll
            for (int r = 0; r < 8; r++) {
                float lo, hi;
                unpack2(lo, hi, acc[r][cp]);
                float s0 = zn[r] - lo;
                unsigned u0 = __float_as_uint(s0);
                if (u0 < v3[r])
                    top3_insert(((ull)u0 << 32) | (unsigned)(jt + 2 * cp),
                                k1[r], k2[r], v3[r]);
                float s1 = zn[r] - hi;
                unsigned u1 = __float_as_uint(s1);
                if (u1 < v3[r])
                    top3_insert(((ull)u1 << 32) | (unsigned)(jt + 2 * cp + 1),
                                k1[r], k2[r], v3[r]);
            }
        }
    }

    // block merge: 48 items per row -> block best-2 keys + exact 3rd value
    __syncthreads();
    char* mbuf = reinterpret_cast<char*>(&e_s[0][0][0]);
    ull* K1 = reinterpret_cast<ull*>(mbuf);            // [64][16]
    ull* K2 = reinterpret_cast<ull*>(mbuf + 8192);     // [64][16]
    unsigned* V3 = reinterpret_cast<unsigned*>(mbuf + 16384);  // [64][16]
    int tn = tid & 15;
#pragma unroll
    for (int r = 0; r < 8; r++) {
        K1[(tm8 + r) * 16 + tn] = k1[r];
        K2[(tm8 + r) * 16 + tn] = k2[r];
        V3[(tm8 + r) * 16 + tn] = v3[r];
    }
    __syncthreads();
    if (tid < 64) {
        int row = tid;
        ull bk1 = ~0ULL, bk2 = ~0ULL;
        unsigned bv3 = 0xFFFFFFFFu;
        for (int q = 0; q < 16; q++) {
            top3_insert(K1[row * 16 + q], bk1, bk2, bv3);
            top3_insert(K2[row * 16 + q], bk1, bk2, bv3);
            top3_insert(((ull)V3[row * 16 + q] << 32) | 0xFFFFFFFFull, bk1, bk2, bv3);
        }
        int o = (row0 + row) * JSPLIT + jsplit;
        g_k1[o] = bk1;
        g_k2[o] = bk2;
        g_v3[o] = bv3;
    }
}

// ---------------------------------------------------------------------------
// Merge per row: global window, exact re-rank of candidates (proven R3 chain),
// or flag row for full fallback if any block had >=3 in-window values.
// ---------------------------------------------------------------------------
__global__ void merge_exact_kernel(const float* __restrict__ e) {
    int b = blockIdx.x * 256 + threadIdx.x;
    float zn = g_znorm[b];
    // window: 2*ulp(zn) + slack
    float ulp = ldexpf(1.0f, ilogbf(fmaxf(zn, 1e-30f)) - 23);
    float W = 2.0f * ulp + 1e-6f;

    ull k1v[JSPLIT], k2v[JSPLIT];
    unsigned v3v[JSPLIT];
    unsigned mu = 0xFFFFFFFFu;
#pragma unroll
    for (int s = 0; s < JSPLIT; s++) {
        k1v[s] = g_k1[b * JSPLIT + s];
        k2v[s] = g_k2[b * JSPLIT + s];
        v3v[s] = g_v3[b * JSPLIT + s];
        unsigned sc = (unsigned)(k1v[s] >> 32);
        if (sc < mu) mu = sc;
    }
    float thr = __uint_as_float(mu) + W;
    unsigned thr_u = __float_as_uint(thr);

    int cj[2 * JSPLIT];
    int nc = 0;
    bool flag = false;
#pragma unroll
    for (int s = 0; s < JSPLIT; s++) {
        if ((unsigned)(k1v[s] >> 32) <= thr_u) cj[nc++] = (int)(unsigned)k1v[s];
        if ((unsigned)(k2v[s] >> 32) <= thr_u) cj[nc++] = (int)(unsigned)k2v[s];
        if (v3v[s] <= thr_u) flag = true;
    }
    if (flag) {
        int p = atomicAdd(&g_fbn, 1);
        g_fb[p] = b;
        return;
    }
    // exact chain on candidates
    float zfr[NKF];
    const float4* zr4 = reinterpret_cast<const float4*>(&g_zf2R[b * NKF]);
#pragma unroll
    for (int i = 0; i < 16; i++) {
        float4 v = zr4[i];
        zfr[i * 4] = v.x; zfr[i * 4 + 1] = v.y;
        zfr[i * 4 + 2] = v.z; zfr[i * 4 + 3] = v.w;
    }
    float bestd = FLT_MAX;
    int bestj = 0x7FFFFFFF;
    for (int i = 0; i < nc; i++) {
        int j = cj[i];
        const float* er = e + (size_t)j * NDIM;
        float acc = 0.f;
#pragma unroll
        for (int k = 0; k < NDIM; k++)
            acc = fmaf(zfr[kf_of_k(k)], er[k], acc);
        float d = zn - acc;
        if (d < bestd || (d == bestd && j < bestj)) { bestd = d; bestj = j; }
    }
    g_idx[b] = bestj;
}

// ---------------------------------------------------------------------------
// Fallback: full exact scan for flagged rows (expected none).
// ---------------------------------------------------------------------------
__global__ void fallback_kernel(const float* __restrict__ e) {
    __shared__ float zfs[NKF];
    __shared__ ull slot;
    int n = g_fbn;
    for (int fi = blockIdx.x; fi < n; fi += gridDim.x) {
        int b = g_fb[fi];
        if (threadIdx.x < NKF) zfs[threadIdx.x] = g_zf2R[b * NKF + threadIdx.x];
        if (threadIdx.x == 0) slot = ~0ULL;
        __syncthreads();
        float zn = g_znorm[b];
        ull lb = ~0ULL;
        for (int j = threadIdx.x; j < NJ; j += 256) {
            const float* er = e + (size_t)j * NDIM;
            float acc = 0.f;
#pragma unroll
            for (int k = 0; k < NDIM; k++)
                acc = fmaf(zfs[kf_of_k(k)], er[k], acc);
            float d = zn - acc;
            ull key = ((ull)__float_as_uint(d) << 32) | (unsigned)j;
            if (key < lb) lb = key;
        }
        atomicMin(&slot, lb);
        __syncthreads();
        if (threadIdx.x == 0) g_idx[b] = (int)(slot & 0xFFFFFFFFu);
        __syncthreads();
    }
}

// ---------------------------------------------------------------------------
// Gather z_q, write transposed output replicating z + fl(z_q - z), stats.
// ---------------------------------------------------------------------------
__global__ void gather_stats_kernel(const float* __restrict__ z,
                                    const float* __restrict__ e,
                                    float* __restrict__ outF, int out_size) {
    int t = blockIdx.x * 256 + threadIdx.x;
    int g0 = t * 4;
    int b = g0 >> 7;
    int i0 = g0 & 127;
    int j = g_idx[b];
    float4 zv = *reinterpret_cast<const float4*>(z + g0);
    float4 qv = *reinterpret_cast<const float4*>(e + (size_t)j * NDIM + i0);

    float q[4] = {qv.x, qv.y, qv.z, qv.w};
    float zz[4] = {zv.x, zv.y, zv.z, zv.w};
    float d[4], o[4];
#pragma unroll
    for (int u = 0; u < 4; u++) {
        d[u] = __fsub_rn(q[u], zz[u]);
        o[u] = __fadd_rn(zz[u], d[u]);
    }
    int c = i0 >> 3, h = (i0 >> 2) & 1;
    int ob = b * 128 + c * 2 + h;
    outF[ob]      = o[0];
    outF[ob + 32] = o[1];
    outF[ob + 64] = o[2];
    outF[ob + 96] = o[3];
    if (i0 == 0 && out_size >= N_ELEM + 1 + NB)
        outF[N_ELEM + 1 + b] = (float)j;

    float sd2 = 0.f, s1 = 0.f, s2 = 0.f, sxx = 0.f, syy = 0.f, sxy = 0.f;
#pragma unroll
    for (int u = 0; u < 4; u++) {
        sd2 = fmaf(d[u], d[u], sd2);
        s1 += q[u];
        s2 += zz[u];
        sxx = fmaf(q[u], q[u], sxx);
        syy = fmaf(zz[u], zz[u], syy);
        sxy = fmaf(q[u], zz[u], sxy);
    }
#pragma unroll
    for (int off = 16; off; off >>= 1) {
        sd2 += __shfl_down_sync(0xFFFFFFFFu, sd2, off);
        s1  += __shfl_down_sync(0xFFFFFFFFu, s1, off);
        s2  += __shfl_down_sync(0xFFFFFFFFu, s2, off);
        sxx += __shfl_down_sync(0xFFFFFFFFu, sxx, off);
        syy += __shfl_down_sync(0xFFFFFFFFu, syy, off);
        sxy += __shfl_down_sync(0xFFFFFFFFu, sxy, off);
    }
    __shared__ float sm[8][6];
    int wid = threadIdx.x >> 5, lane = threadIdx.x & 31;
    if (lane == 0) {
        sm[wid][0] = sd2; sm[wid][1] = s1; sm[wid][2] = s2;
        sm[wid][3] = sxx; sm[wid][4] = syy; sm[wid][5] = sxy;
    }
    __syncthreads();
    if (threadIdx.x < 6) {
        float a = 0.f;
#pragma unroll
        for (int w = 0; w < 8; w++) a += sm[w][threadIdx.x];
        g_partials[blockIdx.x * 6 + threadIdx.x] = a;
    }
}

// ---------------------------------------------------------------------------
__global__ void final_reduce_kernel(float* __restrict__ outF, int out_size) {
    __shared__ double smr[256];
    __shared__ double tot[6];
    double acc[6] = {0, 0, 0, 0, 0, 0};
    for (int p = threadIdx.x; p < N_STAT_BLOCKS; p += 256) {
#pragma unroll
        for (int s = 0; s < 6; s++) acc[s] += (double)g_partials[p * 6 + s];
    }
    for (int s = 0; s < 6; s++) {
        smr[threadIdx.x] = acc[s];
        __syncthreads();
        for (int off = 128; off > 0; off >>= 1) {
            if (threadIdx.x < off) smr[threadIdx.x] += smr[threadIdx.x + off];
            __syncthreads();
        }
        if (threadIdx.x == 0) tot[s] = smr[0];
        __syncthreads();
    }
    if (threadIdx.x == 0 && out_size >= N_ELEM + 1) {
        double N = (double)N_ELEM;
        double commit = 1.25 * tot[0] / N;
        double cov = tot[5] - tot[1] * tot[2] / N;
        double vx = tot[3] - tot[1] * tot[1] / N;
        double vy = tot[4] - tot[2] * tot[2] / N;
        double pearson = 0.5 + 0.5 * cov / (sqrt(vx) * sqrt(vy));
        double loss = commit + pearson + 0.01 * (double)g_colmax;
        outF[N_ELEM] = (float)loss;
    }
}

// ---------------------------------------------------------------------------
extern "C" void kernel_launch(void* const* d_in, const int* in_sizes, int n_in,
                              void* d_out, int out_size) {
    const float* z = (const float*)d_in[0];
    const float* e = (const float*)d_in[1];
    float* out = (float*)d_out;

    prep_z_kernel<<<NB / 128, 128>>>(z);
    fold_e_kernel<<<NJ / 128, 128>>>(e);
    colmax1_kernel<<<128, 128>>>(e);
    colmax2_kernel<<<1, 128>>>();
    pass1_kernel<<<256 * JSPLIT, 128>>>();
    merge_exact_kernel<<<NB / 256, 256>>>(e);
    fallback_kernel<<<16, 256>>>(e);
    gather_stats_kernel<<<N_ELEM / 1024, 256>>>(z, e, out, out_size);
    final_reduce_kernel<<<1, 256>>>(out, out_size);
}